// round 1
// baseline (speedup 1.0000x reference)
#include <cuda_runtime.h>
#include <math.h>

#define NB 8192

// ---------------- device scratch ----------------
__device__ float g_out1[NB * 6 * 14 * 14];   // pooled conv1 output (pre-quant)
__device__ float g_out2[NB * 16 * 5 * 5];    // pooled conv2 output (pre-quant)
__device__ float g_out3[NB * 120];           // fc1 output (pre-quant)
__device__ float g_w1q[6 * 3 * 5 * 5];       // quantized integer weights (as float)
__device__ float g_w2q[16 * 6 * 5 * 5];
__device__ float g_fw1q[120 * 400];
__device__ float g_fw2q[10 * 120];
__device__ int   g_max_bits[4];              // 0:|x|max 1:act1max 2:act2max 3:act3max
__device__ float g_ws[4];                    // weight scales: w1,w2,fw1,fw2

__device__ __forceinline__ float clampf(float v, float lo, float hi) {
    return fminf(fmaxf(v, lo), hi);
}

// block-wide max -> atomicMax into g_max_bits[slot]; values are >= 0 so
// int-bit compare == float compare. ALL threads of the block must call this.
__device__ __forceinline__ void block_atomic_max(float v, int slot) {
#pragma unroll
    for (int o = 16; o > 0; o >>= 1)
        v = fmaxf(v, __shfl_xor_sync(0xffffffffu, v, o));
    __shared__ float wmax[8];
    int lane = threadIdx.x & 31, w = threadIdx.x >> 5;
    if (lane == 0) wmax[w] = v;
    __syncthreads();
    if (w == 0) {
        int nw = (blockDim.x + 31) >> 5;
        v = (lane < nw) ? wmax[lane] : 0.f;
#pragma unroll
        for (int o = 4; o > 0; o >>= 1)
            v = fmaxf(v, __shfl_xor_sync(0xffffffffu, v, o));
        if (lane == 0) atomicMax(&g_max_bits[slot], __float_as_int(v));
    }
}

// ---------------- prep: zero maxima, weight scales + pre-quantized weights ----
__global__ void k_prep(const float* __restrict__ w1, const float* __restrict__ w2,
                       const float* __restrict__ fw1, const float* __restrict__ fw2)
{
    if (blockIdx.x == 0 && threadIdx.x < 4) g_max_bits[threadIdx.x] = 0;

    const float* src; float* dst; int n;
    switch (blockIdx.x) {
        case 0:  src = w1;  dst = g_w1q;  n = 450;   break;
        case 1:  src = w2;  dst = g_w2q;  n = 2400;  break;
        case 2:  src = fw1; dst = g_fw1q; n = 48000; break;
        default: src = fw2; dst = g_fw2q; n = 1200;  break;
    }
    float m = 0.f;
    for (int i = threadIdx.x; i < n; i += blockDim.x)
        m = fmaxf(m, fabsf(src[i]));
#pragma unroll
    for (int o = 16; o > 0; o >>= 1)
        m = fmaxf(m, __shfl_xor_sync(0xffffffffu, m, o));
    __shared__ float smax[8];
    __shared__ float sscale;
    int lane = threadIdx.x & 31, w = threadIdx.x >> 5;
    if (lane == 0) smax[w] = m;
    __syncthreads();
    if (threadIdx.x == 0) {
        float mm = smax[0];
        for (int i = 1; i < (int)((blockDim.x + 31) >> 5); i++) mm = fmaxf(mm, smax[i]);
        float s = mm / 127.0f + 1e-12f;
        g_ws[blockIdx.x] = s;
        sscale = s;
    }
    __syncthreads();
    float s = sscale;
    for (int i = threadIdx.x; i < n; i += blockDim.x)
        dst[i] = clampf(rintf(src[i] / s), -128.f, 127.f);
}

// ---------------- global abs-max of x ----------------
__global__ void k_xmax(const float* __restrict__ x, int n)
{
    float m = 0.f;
    int n4 = n >> 2;
    const float4* x4 = reinterpret_cast<const float4*>(x);
    for (int i = blockIdx.x * blockDim.x + threadIdx.x; i < n4; i += gridDim.x * blockDim.x) {
        float4 v = x4[i];
        m = fmaxf(m, fmaxf(fmaxf(fabsf(v.x), fabsf(v.y)), fmaxf(fabsf(v.z), fabsf(v.w))));
    }
    if (blockIdx.x == 0 && threadIdx.x == 0)
        for (int i = n4 << 2; i < n; i++) m = fmaxf(m, fabsf(x[i]));
    block_atomic_max(m, 0);
}

// ---------------- conv1 + bias + relu + maxpool, fused ----------------
// in: x [N,3,32,32]; out: g_out1 [N,6,14,14]; tracks act max in slot 1
__global__ void __launch_bounds__(256) k_conv1(const float* __restrict__ x,
                                               const float* __restrict__ b1,
                                               int nimg)
{
    __shared__ float sx[3 * 3072];
    __shared__ float sw[450];
    const float s0 = __int_as_float(g_max_bits[0]) / 127.0f + 1e-12f;
    const int base = blockIdx.x * 3;
    const int count = min(3, nimg - base);

    for (int i = threadIdx.x; i < count * 3072; i += 256) {
        float v = x[(size_t)base * 3072 + i];
        sx[i] = clampf(rintf(v / s0), -128.f, 127.f);
    }
    for (int i = threadIdx.x; i < 450; i += 256) sw[i] = g_w1q[i];
    __syncthreads();

    float lmax = 0.f;
    int img_l = threadIdx.x / 84;
    int r = threadIdx.x % 84;
    if (img_l < count) {
        int co = r / 14, ph = r % 14;
        const float* xim = sx + img_l * 3072;
        const float* wk = sw + co * 75;
        float acc0[28], acc1[28];
#pragma unroll
        for (int i = 0; i < 28; i++) { acc0[i] = 0.f; acc1[i] = 0.f; }
        for (int ci = 0; ci < 3; ci++) {
            const float* xc = xim + ci * 1024 + (2 * ph) * 32;
            const float* wc = wk + ci * 25;
#pragma unroll
            for (int r6 = 0; r6 < 6; r6++) {
                float xv[32];
#pragma unroll
                for (int j = 0; j < 32; j++) xv[j] = xc[r6 * 32 + j];
                if (r6 < 5) {
#pragma unroll
                    for (int kw = 0; kw < 5; kw++) {
                        float wv = wc[r6 * 5 + kw];
#pragma unroll
                        for (int ow = 0; ow < 28; ow++)
                            acc0[ow] = fmaf(wv, xv[ow + kw], acc0[ow]);
                    }
                }
                if (r6 >= 1) {
#pragma unroll
                    for (int kw = 0; kw < 5; kw++) {
                        float wv = wc[(r6 - 1) * 5 + kw];
#pragma unroll
                        for (int ow = 0; ow < 28; ow++)
                            acc1[ow] = fmaf(wv, xv[ow + kw], acc1[ow]);
                    }
                }
            }
        }
        float sp = s0 * g_ws[0];
        float bdq = rintf(b1[co] / sp) * sp;
        float* op = g_out1 + (size_t)(base + img_l) * 1176 + co * 196 + ph * 14;
#pragma unroll
        for (int pw = 0; pw < 14; pw++) {
            float m = fmaxf(fmaxf(acc0[2 * pw], acc0[2 * pw + 1]),
                            fmaxf(acc1[2 * pw], acc1[2 * pw + 1]));
            float v = fmaxf(fmaf(sp, m, bdq), 0.f);
            lmax = fmaxf(lmax, v);
            op[pw] = v;
        }
    }
    block_atomic_max(lmax, 1);
}

// ---------------- conv2 + bias + relu + maxpool, fused ----------------
// in: g_out1 (quantized on load); out: g_out2 [N,16,5,5]; max -> slot 2
__global__ void __launch_bounds__(256) k_conv2(const float* __restrict__ b2, int nimg)
{
    __shared__ float sx[3 * 1176];
    __shared__ float sw[2400];
    const float s1 = __int_as_float(g_max_bits[1]) / 255.0f + 1e-12f;
    const int base = blockIdx.x * 3;
    const int count = min(3, nimg - base);

    for (int i = threadIdx.x; i < count * 1176; i += 256) {
        float v = g_out1[(size_t)base * 1176 + i];
        sx[i] = clampf(rintf(v / s1), 0.f, 255.f);
    }
    for (int i = threadIdx.x; i < 2400; i += 256) sw[i] = g_w2q[i];
    __syncthreads();

    float lmax = 0.f;
    int img_l = threadIdx.x / 80;
    int r = threadIdx.x % 80;
    if (img_l < count) {
        int co = r / 5, ph = r % 5;
        const float* xim = sx + img_l * 1176;
        const float* wk = sw + co * 150;
        float acc0[10], acc1[10];
#pragma unroll
        for (int i = 0; i < 10; i++) { acc0[i] = 0.f; acc1[i] = 0.f; }
        for (int ci = 0; ci < 6; ci++) {
            const float* xc = xim + ci * 196 + (2 * ph) * 14;
            const float* wc = wk + ci * 25;
#pragma unroll
            for (int r6 = 0; r6 < 6; r6++) {
                float xv[14];
#pragma unroll
                for (int j = 0; j < 14; j++) xv[j] = xc[r6 * 14 + j];
                if (r6 < 5) {
#pragma unroll
                    for (int kw = 0; kw < 5; kw++) {
                        float wv = wc[r6 * 5 + kw];
#pragma unroll
                        for (int ow = 0; ow < 10; ow++)
                            acc0[ow] = fmaf(wv, xv[ow + kw], acc0[ow]);
                    }
                }
                if (r6 >= 1) {
#pragma unroll
                    for (int kw = 0; kw < 5; kw++) {
                        float wv = wc[(r6 - 1) * 5 + kw];
#pragma unroll
                        for (int ow = 0; ow < 10; ow++)
                            acc1[ow] = fmaf(wv, xv[ow + kw], acc1[ow]);
                    }
                }
            }
        }
        float sp = s1 * g_ws[1];
        float bdq = rintf(b2[co] / sp) * sp;
        float* op = g_out2 + (size_t)(base + img_l) * 400 + co * 25 + ph * 5;
#pragma unroll
        for (int pw = 0; pw < 5; pw++) {
            float m = fmaxf(fmaxf(acc0[2 * pw], acc0[2 * pw + 1]),
                            fmaxf(acc1[2 * pw], acc1[2 * pw + 1]));
            float v = fmaxf(fmaf(sp, m, bdq), 0.f);
            lmax = fmaxf(lmax, v);
            op[pw] = v;
        }
    }
    block_atomic_max(lmax, 2);
}

// ---------------- fc1 + bias + relu ----------------
// 32 rows/block (dynamic smem), 120 compute threads: 8 row-groups x 15 col-groups,
// 4x8 register tile. Weights pre-quantized in g_fw1q via L1. max -> slot 3.
__global__ void __launch_bounds__(128) k_fc1(const float* __restrict__ fb1, int nimg)
{
    extern __shared__ float sa[];  // [32][401]
    const float s2 = __int_as_float(g_max_bits[2]) / 255.0f + 1e-12f;
    const int row0 = blockIdx.x * 32;

    for (int i = threadIdx.x; i < 32 * 400; i += 128) {
        int rr = i / 400, k = i % 400;
        float q = 0.f;
        if (row0 + rr < nimg) {
            float v = g_out2[(size_t)(row0 + rr) * 400 + k];
            q = clampf(rintf(v / s2), 0.f, 255.f);
        }
        sa[rr * 401 + k] = q;
    }
    __syncthreads();

    float lmax = 0.f;
    if (threadIdx.x < 120) {
        int rg = threadIdx.x / 15, cg = threadIdx.x % 15;
        float acc[4][8];
#pragma unroll
        for (int i = 0; i < 4; i++)
#pragma unroll
            for (int j = 0; j < 8; j++) acc[i][j] = 0.f;

        const float* wbase = g_fw1q + cg * 400;   // col = cg + 15*j -> + j*6000
#pragma unroll 2
        for (int k = 0; k < 400; k++) {
            float a0 = sa[(rg * 4 + 0) * 401 + k];
            float a1 = sa[(rg * 4 + 1) * 401 + k];
            float a2 = sa[(rg * 4 + 2) * 401 + k];
            float a3 = sa[(rg * 4 + 3) * 401 + k];
#pragma unroll
            for (int j = 0; j < 8; j++) {
                float wv = __ldg(wbase + j * 6000 + k);
                acc[0][j] = fmaf(a0, wv, acc[0][j]);
                acc[1][j] = fmaf(a1, wv, acc[1][j]);
                acc[2][j] = fmaf(a2, wv, acc[2][j]);
                acc[3][j] = fmaf(a3, wv, acc[3][j]);
            }
        }
        float sp = s2 * g_ws[2];
#pragma unroll
        for (int j = 0; j < 8; j++) {
            int col = cg + 15 * j;
            float bdq = rintf(__ldg(&fb1[col]) / sp) * sp;
#pragma unroll
            for (int i = 0; i < 4; i++) {
                int row = row0 + rg * 4 + i;
                float v = fmaxf(fmaf(sp, acc[i][j], bdq), 0.f);
                lmax = fmaxf(lmax, v);
                if (row < nimg) g_out3[(size_t)row * 120 + col] = v;
            }
        }
    }
    block_atomic_max(lmax, 3);
}

// ---------------- fc2 + bias (final output) ----------------
__global__ void __launch_bounds__(64) k_fc2(const float* __restrict__ fb2,
                                            float* __restrict__ out, int nimg)
{
    __shared__ float sa[64 * 121];
    __shared__ float sw[1200];
    const float s3 = __int_as_float(g_max_bits[3]) / 255.0f + 1e-12f;
    const int row0 = blockIdx.x * 64;

    for (int i = threadIdx.x; i < 1200; i += 64) sw[i] = g_fw2q[i];
    for (int i = threadIdx.x; i < 64 * 120; i += 64) {
        int rr = i / 120, k = i % 120;
        float q = 0.f;
        if (row0 + rr < nimg) {
            float v = g_out3[(size_t)(row0 + rr) * 120 + k];
            q = clampf(rintf(v / s3), 0.f, 255.f);
        }
        sa[rr * 121 + k] = q;
    }
    __syncthreads();

    int row = row0 + threadIdx.x;
    float acc[10];
#pragma unroll
    for (int c = 0; c < 10; c++) acc[c] = 0.f;
    const float* ar = sa + threadIdx.x * 121;
#pragma unroll 4
    for (int k = 0; k < 120; k++) {
        float a = ar[k];
#pragma unroll
        for (int c = 0; c < 10; c++) acc[c] = fmaf(a, sw[c * 120 + k], acc[c]);
    }
    float sp = s3 * g_ws[3];
    if (row < nimg) {
#pragma unroll
        for (int c = 0; c < 10; c++) {
            float bdq = rintf(__ldg(&fb2[c]) / sp) * sp;
            out[(size_t)row * 10 + c] = fmaf(sp, acc[c], bdq);
        }
    }
}

// ---------------- launch ----------------
extern "C" void kernel_launch(void* const* d_in, const int* in_sizes, int n_in,
                              void* d_out, int out_size)
{
    const float* x   = (const float*)d_in[0];
    const float* w1  = (const float*)d_in[1];
    const float* b1  = (const float*)d_in[2];
    const float* w2  = (const float*)d_in[3];
    const float* b2  = (const float*)d_in[4];
    const float* fw1 = (const float*)d_in[5];
    const float* fb1 = (const float*)d_in[6];
    const float* fw2 = (const float*)d_in[7];
    const float* fb2 = (const float*)d_in[8];
    float* out = (float*)d_out;
    const int nimg = in_sizes[0] / (3 * 32 * 32);

    cudaFuncSetAttribute(k_fc1, cudaFuncAttributeMaxDynamicSharedMemorySize,
                         32 * 401 * (int)sizeof(float));

    k_prep<<<4, 256>>>(w1, w2, fw1, fw2);
    k_xmax<<<2048, 256>>>(x, in_sizes[0]);
    k_conv1<<<(nimg + 2) / 3, 256>>>(x, b1, nimg);
    k_conv2<<<(nimg + 2) / 3, 256>>>(b2, nimg);
    k_fc1<<<(nimg + 31) / 32, 128, 32 * 401 * (int)sizeof(float)>>>(fb1, nimg);
    k_fc2<<<(nimg + 63) / 64, 64>>>(fb2, out, nimg);
}

// round 2
// speedup vs baseline: 2.0214x; 2.0214x over previous
#include <cuda_runtime.h>
#include <math.h>

#define NB 8192

// ---------------- device scratch ----------------
__device__ float g_out1[NB * 196 * 6];    // conv1 pooled, NHWC (c=6)
__device__ float g_out2[NB * 25 * 16];    // conv2 pooled, NHWC (c=16)
__device__ float g_out3[NB * 120];        // fc1 out
__device__ __align__(16) int g_w1p[6 * 25];        // packed s8 weights: [co][tap] (3ch+pad)
__device__ __align__(16) int g_w2p[16 * 25 * 2];   // [co][tap][2 words of 4ch]
__device__ __align__(16) int g_fw1p[100 * 120];    // k-major [k_word][col], HWC-permuted
__device__ __align__(16) int g_fw2p[10 * 30];      // [col][k_word]
__device__ int   g_max_bits[4];           // 0:|x|max 1:act1 2:act2 3:act3
__device__ float g_ws[4];                 // weight scales

__device__ __forceinline__ int dp4a_ss(unsigned a, unsigned b, int c) {
    int d; asm("dp4a.s32.s32 %0, %1, %2, %3;" : "=r"(d) : "r"(a), "r"(b), "r"(c)); return d;
}
__device__ __forceinline__ int dp4a_us(unsigned a, unsigned b, int c) {
    int d; asm("dp4a.u32.s32 %0, %1, %2, %3;" : "=r"(d) : "r"(a), "r"(b), "r"(c)); return d;
}
__device__ __forceinline__ int q_s8(float v, float s) {
    int q = __float2int_rn(v / s);
    return min(max(q, -128), 127);
}
__device__ __forceinline__ int q_u8(float v, float s) {
    int q = __float2int_rn(v / s);
    return min(max(q, 0), 255);
}
__device__ __forceinline__ unsigned pack4(int a, int b, int c, int d) {
    return (unsigned)(a & 0xff) | ((unsigned)(b & 0xff) << 8) |
           ((unsigned)(c & 0xff) << 16) | ((unsigned)(d & 0xff) << 24);
}

// block-wide max -> atomicMax into g_max_bits[slot]; v >= 0 so int-bit cmp works.
__device__ __forceinline__ void block_atomic_max(float v, int slot) {
#pragma unroll
    for (int o = 16; o > 0; o >>= 1)
        v = fmaxf(v, __shfl_xor_sync(0xffffffffu, v, o));
    __shared__ float wmax[8];
    int lane = threadIdx.x & 31, w = threadIdx.x >> 5;
    if (lane == 0) wmax[w] = v;
    __syncthreads();
    if (w == 0) {
        int nw = (blockDim.x + 31) >> 5;
        v = (lane < nw) ? wmax[lane] : 0.f;
#pragma unroll
        for (int o = 4; o > 0; o >>= 1)
            v = fmaxf(v, __shfl_xor_sync(0xffffffffu, v, o));
        if (lane == 0) atomicMax(&g_max_bits[slot], __float_as_int(v));
    }
}

// ---------------- prep: zero maxima, weight scales + packed int8 weights ----
__global__ void k_prep(const float* __restrict__ w1, const float* __restrict__ w2,
                       const float* __restrict__ fw1, const float* __restrict__ fw2)
{
    if (blockIdx.x == 0 && threadIdx.x < 4) g_max_bits[threadIdx.x] = 0;

    const float* src; int n;
    switch (blockIdx.x) {
        case 0:  src = w1;  n = 450;   break;
        case 1:  src = w2;  n = 2400;  break;
        case 2:  src = fw1; n = 48000; break;
        default: src = fw2; n = 1200;  break;
    }
    float m = 0.f;
    for (int i = threadIdx.x; i < n; i += blockDim.x)
        m = fmaxf(m, fabsf(src[i]));
#pragma unroll
    for (int o = 16; o > 0; o >>= 1)
        m = fmaxf(m, __shfl_xor_sync(0xffffffffu, m, o));
    __shared__ float smax[8];
    __shared__ float sscale;
    int lane = threadIdx.x & 31, w = threadIdx.x >> 5;
    if (lane == 0) smax[w] = m;
    __syncthreads();
    if (threadIdx.x == 0) {
        float mm = smax[0];
        for (int i = 1; i < (int)((blockDim.x + 31) >> 5); i++) mm = fmaxf(mm, smax[i]);
        float s = mm / 127.0f + 1e-12f;
        g_ws[blockIdx.x] = s;
        sscale = s;
    }
    __syncthreads();
    float s = sscale;

    if (blockIdx.x == 0) {
        // w1 [6,3,5,5] -> [co][tap] word of (c0,c1,c2,0)
        for (int t = threadIdx.x; t < 150; t += blockDim.x) {
            int co = t / 25, tap = t % 25;
            g_w1p[t] = (int)pack4(q_s8(w1[co * 75 + tap], s),
                                  q_s8(w1[co * 75 + 25 + tap], s),
                                  q_s8(w1[co * 75 + 50 + tap], s), 0);
        }
    } else if (blockIdx.x == 1) {
        // w2 [16,6,5,5] -> [co][tap][wi] words of 4 channels (6 real + 2 pad)
        for (int t = threadIdx.x; t < 800; t += blockDim.x) {
            int co = t / 50, rem = t % 50, tap = rem / 2, wi = rem % 2;
            int q[4];
#pragma unroll
            for (int b = 0; b < 4; b++) {
                int ci = wi * 4 + b;
                q[b] = (ci < 6) ? q_s8(w2[co * 150 + ci * 25 + tap], s) : 0;
            }
            g_w2p[t] = (int)pack4(q[0], q[1], q[2], q[3]);
        }
    } else if (blockIdx.x == 2) {
        // fw1 [120,400] -> k-major [k_word][col]; our act idx i = pix*16+c maps
        // to ref k = c*25 + pix
        for (int t = threadIdx.x; t < 12000; t += blockDim.x) {
            int k = t / 120, col = t % 120;
            int q[4];
#pragma unroll
            for (int b = 0; b < 4; b++) {
                int i = 4 * k + b;
                int c = i & 15, pix = i >> 4;
                q[b] = q_s8(fw1[col * 400 + c * 25 + pix], s);
            }
            g_fw1p[t] = (int)pack4(q[0], q[1], q[2], q[3]);
        }
    } else {
        // fw2 [10,120] -> [col][k_word]
        for (int t = threadIdx.x; t < 300; t += blockDim.x) {
            int col = t / 30, j = t % 30;
            g_fw2p[t] = (int)pack4(q_s8(fw2[col * 120 + 4 * j + 0], s),
                                   q_s8(fw2[col * 120 + 4 * j + 1], s),
                                   q_s8(fw2[col * 120 + 4 * j + 2], s),
                                   q_s8(fw2[col * 120 + 4 * j + 3], s));
        }
    }
}

// ---------------- global abs-max of x ----------------
__global__ void k_xmax(const float* __restrict__ x, int n)
{
    float m = 0.f;
    int n4 = n >> 2;
    const float4* x4 = reinterpret_cast<const float4*>(x);
    for (int i = blockIdx.x * blockDim.x + threadIdx.x; i < n4; i += gridDim.x * blockDim.x) {
        float4 v = x4[i];
        m = fmaxf(m, fmaxf(fmaxf(fabsf(v.x), fabsf(v.y)), fmaxf(fabsf(v.z), fabsf(v.w))));
    }
    if (blockIdx.x == 0 && threadIdx.x == 0)
        for (int i = n4 << 2; i < n; i++) m = fmaxf(m, fabsf(x[i]));
    block_atomic_max(m, 0);
}

// ---------------- conv1 + bias + relu + maxpool (dp4a) ----------------
__global__ void __launch_bounds__(256) k_conv1(const float* __restrict__ x,
                                               const float* __restrict__ b1,
                                               int nimg)
{
    __shared__ unsigned sx[3 * 1024];   // [img][32*32] packed NHWC4
    __shared__ int sw[150];
    const float s0 = __int_as_float(g_max_bits[0]) / 127.0f + 1e-12f;
    const int base = blockIdx.x * 3;
    const int count = min(3, nimg - base);

    for (int i = threadIdx.x; i < count * 1024; i += 256) {
        int img = i >> 10, p = i & 1023;
        const float* xp = x + (size_t)(base + img) * 3072 + p;
        sx[i] = pack4(q_s8(xp[0], s0), q_s8(xp[1024], s0), q_s8(xp[2048], s0), 0);
    }
    for (int i = threadIdx.x; i < 150; i += 256) sw[i] = g_w1p[i];
    __syncthreads();

    float lmax = 0.f;
    int img_l = threadIdx.x / 84;
    int r = threadIdx.x % 84;
    if (img_l < count) {
        int co = r / 14, ph = r % 14;
        const unsigned* xim = sx + img_l * 1024 + (2 * ph) * 32;
        const int* wk = sw + co * 25;
        int acc0[28], acc1[28];
#pragma unroll
        for (int i = 0; i < 28; i++) { acc0[i] = 0; acc1[i] = 0; }
#pragma unroll
        for (int r6 = 0; r6 < 6; r6++) {
            unsigned xv[32];
#pragma unroll
            for (int j = 0; j < 32; j++) xv[j] = xim[r6 * 32 + j];
            if (r6 < 5) {
#pragma unroll
                for (int kw = 0; kw < 5; kw++) {
                    unsigned wv = (unsigned)wk[r6 * 5 + kw];
#pragma unroll
                    for (int ow = 0; ow < 28; ow++)
                        acc0[ow] = dp4a_ss(xv[ow + kw], wv, acc0[ow]);
                }
            }
            if (r6 >= 1) {
#pragma unroll
                for (int kw = 0; kw < 5; kw++) {
                    unsigned wv = (unsigned)wk[(r6 - 1) * 5 + kw];
#pragma unroll
                    for (int ow = 0; ow < 28; ow++)
                        acc1[ow] = dp4a_ss(xv[ow + kw], wv, acc1[ow]);
                }
            }
        }
        float sp = s0 * g_ws[0];
        int qb = __float2int_rn(b1[co] / sp);
        float* op = g_out1 + ((size_t)(base + img_l) * 196 + ph * 14) * 6 + co;
#pragma unroll
        for (int pw = 0; pw < 14; pw++) {
            int m = max(max(acc0[2 * pw], acc0[2 * pw + 1]),
                        max(acc1[2 * pw], acc1[2 * pw + 1]));
            float v = sp * (float)max(m + qb, 0);
            lmax = fmaxf(lmax, v);
            op[pw * 6] = v;
        }
    }
    block_atomic_max(lmax, 1);
}

// ---------------- conv2 + bias + relu + maxpool (dp4a) ----------------
__global__ void __launch_bounds__(256) k_conv2(const float* __restrict__ b2, int nimg)
{
    __shared__ unsigned sx[3 * 392];    // [img][14*14][2] packed NHWC8
    __shared__ int sw[800];
    const float s1 = __int_as_float(g_max_bits[1]) / 255.0f + 1e-12f;
    const int base = blockIdx.x * 3;
    const int count = min(3, nimg - base);

    for (int i = threadIdx.x; i < count * 196; i += 256) {
        int img = i / 196, p = i % 196;
        const float2* ap = (const float2*)(g_out1 + ((size_t)(base + img) * 196 + p) * 6);
        float2 v0 = ap[0], v1 = ap[1], v2 = ap[2];
        sx[i * 2]     = pack4(q_u8(v0.x, s1), q_u8(v0.y, s1), q_u8(v1.x, s1), q_u8(v1.y, s1));
        sx[i * 2 + 1] = pack4(q_u8(v2.x, s1), q_u8(v2.y, s1), 0, 0);
    }
    for (int i = threadIdx.x; i < 800; i += 256) sw[i] = g_w2p[i];
    __syncthreads();

    float lmax = 0.f;
    int img_l = threadIdx.x / 80;
    int r = threadIdx.x % 80;
    if (img_l < count) {
        int co = r / 5, ph = r % 5;
        const unsigned* xim = sx + img_l * 392 + (2 * ph) * 28;
        const int* wk = sw + co * 50;
        int acc0[10], acc1[10];
#pragma unroll
        for (int i = 0; i < 10; i++) { acc0[i] = 0; acc1[i] = 0; }
#pragma unroll
        for (int r6 = 0; r6 < 6; r6++) {
            unsigned xv[28];
#pragma unroll
            for (int j = 0; j < 28; j++) xv[j] = xim[r6 * 28 + j];
            if (r6 < 5) {
#pragma unroll
                for (int kw = 0; kw < 5; kw++) {
                    unsigned w0 = (unsigned)wk[(r6 * 5 + kw) * 2];
                    unsigned w1 = (unsigned)wk[(r6 * 5 + kw) * 2 + 1];
#pragma unroll
                    for (int ow = 0; ow < 10; ow++)
                        acc0[ow] = dp4a_us(xv[(ow + kw) * 2 + 1], w1,
                                   dp4a_us(xv[(ow + kw) * 2], w0, acc0[ow]));
                }
            }
            if (r6 >= 1) {
#pragma unroll
                for (int kw = 0; kw < 5; kw++) {
                    unsigned w0 = (unsigned)wk[((r6 - 1) * 5 + kw) * 2];
                    unsigned w1 = (unsigned)wk[((r6 - 1) * 5 + kw) * 2 + 1];
#pragma unroll
                    for (int ow = 0; ow < 10; ow++)
                        acc1[ow] = dp4a_us(xv[(ow + kw) * 2 + 1], w1,
                                   dp4a_us(xv[(ow + kw) * 2], w0, acc1[ow]));
                }
            }
        }
        float sp = s1 * g_ws[1];
        int qb = __float2int_rn(b2[co] / sp);
        float* op = g_out2 + ((size_t)(base + img_l) * 25 + ph * 5) * 16 + co;
#pragma unroll
        for (int pw = 0; pw < 5; pw++) {
            int m = max(max(acc0[2 * pw], acc0[2 * pw + 1]),
                        max(acc1[2 * pw], acc1[2 * pw + 1]));
            float v = sp * (float)max(m + qb, 0);
            lmax = fmaxf(lmax, v);
            op[pw * 16] = v;
        }
    }
    block_atomic_max(lmax, 2);
}

// ---------------- fc1 + bias + relu (dp4a, smem weights) ----------------
// 32 rows/block; dyn smem: act [32][101] words + weights k-major [100][120] words.
// 240 compute threads: 8 row-groups (4 rows) x 30 col-groups (4 cols, int4 LDS).
__global__ void __launch_bounds__(256) k_fc1(const float* __restrict__ fb1, int nimg)
{
    extern __shared__ unsigned dyn[];
    unsigned* sa = dyn;                 // 32*101 = 3232 words
    int* sw = (int*)(dyn + 32 * 101);   // 12000 words (16B-aligned: 3232*4=12928)
    const float s2 = __int_as_float(g_max_bits[2]) / 255.0f + 1e-12f;
    const int row0 = blockIdx.x * 32;

    for (int i = threadIdx.x; i < 3000; i += 256)
        ((int4*)sw)[i] = ((const int4*)g_fw1p)[i];
    for (int i = threadIdx.x; i < 3200; i += 256) {
        int rr = i / 100, j = i % 100;
        unsigned wv = 0;
        if (row0 + rr < nimg) {
            float4 v = *(const float4*)(g_out2 + (size_t)(row0 + rr) * 400 + 4 * j);
            wv = pack4(q_u8(v.x, s2), q_u8(v.y, s2), q_u8(v.z, s2), q_u8(v.w, s2));
        }
        sa[rr * 101 + j] = wv;
    }
    __syncthreads();

    float lmax = 0.f;
    if (threadIdx.x < 240) {
        int rg = threadIdx.x / 30, cg = threadIdx.x % 30;
        int acc[4][4];
#pragma unroll
        for (int i = 0; i < 4; i++)
#pragma unroll
            for (int j = 0; j < 4; j++) acc[i][j] = 0;

        const unsigned* ap = sa + (rg * 4) * 101;
#pragma unroll 4
        for (int k = 0; k < 100; k++) {
            unsigned a0 = ap[k], a1 = ap[101 + k], a2 = ap[202 + k], a3 = ap[303 + k];
            int4 w = *(const int4*)(sw + k * 120 + cg * 4);
            acc[0][0] = dp4a_us(a0, (unsigned)w.x, acc[0][0]);
            acc[0][1] = dp4a_us(a0, (unsigned)w.y, acc[0][1]);
            acc[0][2] = dp4a_us(a0, (unsigned)w.z, acc[0][2]);
            acc[0][3] = dp4a_us(a0, (unsigned)w.w, acc[0][3]);
            acc[1][0] = dp4a_us(a1, (unsigned)w.x, acc[1][0]);
            acc[1][1] = dp4a_us(a1, (unsigned)w.y, acc[1][1]);
            acc[1][2] = dp4a_us(a1, (unsigned)w.z, acc[1][2]);
            acc[1][3] = dp4a_us(a1, (unsigned)w.w, acc[1][3]);
            acc[2][0] = dp4a_us(a2, (unsigned)w.x, acc[2][0]);
            acc[2][1] = dp4a_us(a2, (unsigned)w.y, acc[2][1]);
            acc[2][2] = dp4a_us(a2, (unsigned)w.z, acc[2][2]);
            acc[2][3] = dp4a_us(a2, (unsigned)w.w, acc[2][3]);
            acc[3][0] = dp4a_us(a3, (unsigned)w.x, acc[3][0]);
            acc[3][1] = dp4a_us(a3, (unsigned)w.y, acc[3][1]);
            acc[3][2] = dp4a_us(a3, (unsigned)w.z, acc[3][2]);
            acc[3][3] = dp4a_us(a3, (unsigned)w.w, acc[3][3]);
        }
        float sp = s2 * g_ws[2];
#pragma unroll
        for (int j = 0; j < 4; j++) {
            int col = cg * 4 + j;
            int qb = __float2int_rn(__ldg(&fb1[col]) / sp);
#pragma unroll
            for (int i = 0; i < 4; i++) {
                int row = row0 + rg * 4 + i;
                float v = sp * (float)max(acc[i][j] + qb, 0);
                lmax = fmaxf(lmax, v);
                if (row < nimg) g_out3[(size_t)row * 120 + col] = v;
            }
        }
    }
    block_atomic_max(lmax, 3);
}

// ---------------- fc2 + bias (dp4a, final output) ----------------
__global__ void __launch_bounds__(64) k_fc2(const float* __restrict__ fb2,
                                            float* __restrict__ out, int nimg)
{
    __shared__ unsigned sa[64 * 31];
    __shared__ int sw[300];
    const float s3 = __int_as_float(g_max_bits[3]) / 255.0f + 1e-12f;
    const int row0 = blockIdx.x * 64;

    for (int i = threadIdx.x; i < 300; i += 64) sw[i] = g_fw2p[i];
    for (int i = threadIdx.x; i < 64 * 30; i += 64) {
        int rr = i / 30, j = i % 30;
        unsigned wv = 0;
        if (row0 + rr < nimg) {
            float4 v = *(const float4*)(g_out3 + (size_t)(row0 + rr) * 120 + 4 * j);
            wv = pack4(q_u8(v.x, s3), q_u8(v.y, s3), q_u8(v.z, s3), q_u8(v.w, s3));
        }
        sa[rr * 31 + j] = wv;
    }
    __syncthreads();

    int row = row0 + threadIdx.x;
    int acc[10];
#pragma unroll
    for (int c = 0; c < 10; c++) acc[c] = 0;
    const unsigned* ar = sa + threadIdx.x * 31;
#pragma unroll 5
    for (int k = 0; k < 30; k++) {
        unsigned a = ar[k];
#pragma unroll
        for (int c = 0; c < 10; c++)
            acc[c] = dp4a_us(a, (unsigned)sw[c * 30 + k], acc[c]);
    }
    float sp = s3 * g_ws[3];
    if (row < nimg) {
#pragma unroll
        for (int c = 0; c < 10; c++) {
            int qb = __float2int_rn(__ldg(&fb2[c]) / sp);
            out[(size_t)row * 10 + c] = sp * (float)(acc[c] + qb);
        }
    }
}

// ---------------- launch ----------------
extern "C" void kernel_launch(void* const* d_in, const int* in_sizes, int n_in,
                              void* d_out, int out_size)
{
    const float* x   = (const float*)d_in[0];
    const float* w1  = (const float*)d_in[1];
    const float* b1  = (const float*)d_in[2];
    const float* w2  = (const float*)d_in[3];
    const float* b2  = (const float*)d_in[4];
    const float* fw1 = (const float*)d_in[5];
    const float* fb1 = (const float*)d_in[6];
    const float* fw2 = (const float*)d_in[7];
    const float* fb2 = (const float*)d_in[8];
    float* out = (float*)d_out;
    const int nimg = in_sizes[0] / (3 * 32 * 32);

    const int fc1_dyn = (32 * 101 + 12000) * (int)sizeof(int);
    cudaFuncSetAttribute(k_fc1, cudaFuncAttributeMaxDynamicSharedMemorySize, fc1_dyn);

    k_prep<<<4, 256>>>(w1, w2, fw1, fw2);
    k_xmax<<<2048, 256>>>(x, in_sizes[0]);
    k_conv1<<<(nimg + 2) / 3, 256>>>(x, b1, nimg);
    k_conv2<<<(nimg + 2) / 3, 256>>>(b2, nimg);
    k_fc1<<<(nimg + 31) / 32, 256, fc1_dyn>>>(fb1, nimg);
    k_fc2<<<(nimg + 63) / 64, 64>>>(fb2, out, nimg);
}

// round 3
// speedup vs baseline: 2.6143x; 1.2933x over previous
#include <cuda_runtime.h>
#include <math.h>

#define NB 8192

// ---------------- device scratch ----------------
__device__ float g_out1[NB * 196 * 6];    // conv1 pooled, NHWC (c=6)
__device__ float g_out2[NB * 25 * 16];    // conv2 pooled, NHWC (c=16)
__device__ float g_out3[NB * 120];        // fc1 out
__device__ __align__(16) int g_w1p[6 * 25];        // packed s8 weights: [co][tap] (3ch+pad)
__device__ __align__(16) int g_w2p[16 * 25 * 2];   // [co][tap][2 words of 4ch]
__device__ __align__(16) int g_fw1p[100 * 120];    // k-major [k_word][col], HWC-permuted
__device__ __align__(16) int g_fw2p[10 * 30];      // [col][k_word]
__device__ int   g_max_bits[4];           // 0:|x|max 1:act1 2:act2 3:act3
__device__ float g_ws[4];                 // weight scales

__device__ __forceinline__ int dp4a_ss(unsigned a, unsigned b, int c) {
    int d; asm("dp4a.s32.s32 %0, %1, %2, %3;" : "=r"(d) : "r"(a), "r"(b), "r"(c)); return d;
}
__device__ __forceinline__ int dp4a_us(unsigned a, unsigned b, int c) {
    int d; asm("dp4a.u32.s32 %0, %1, %2, %3;" : "=r"(d) : "r"(a), "r"(b), "r"(c)); return d;
}
__device__ __forceinline__ int q_s8m(float v, float inv) {
    int q = __float2int_rn(v * inv);
    return min(max(q, -128), 127);
}
__device__ __forceinline__ int q_u8m(float v, float inv) {
    int q = __float2int_rn(v * inv);
    return min(max(q, 0), 255);
}
__device__ __forceinline__ unsigned pack4(int a, int b, int c, int d) {
    return (unsigned)(a & 0xff) | ((unsigned)(b & 0xff) << 8) |
           ((unsigned)(c & 0xff) << 16) | ((unsigned)(d & 0xff) << 24);
}

// block-wide max -> atomicMax into g_max_bits[slot]; v >= 0 so int-bit cmp works.
// ALL threads of the block must call this.
__device__ __forceinline__ void block_atomic_max(float v, int slot) {
#pragma unroll
    for (int o = 16; o > 0; o >>= 1)
        v = fmaxf(v, __shfl_xor_sync(0xffffffffu, v, o));
    __shared__ float wmax[16];
    int lane = threadIdx.x & 31, w = threadIdx.x >> 5;
    if (lane == 0) wmax[w] = v;
    __syncthreads();
    if (w == 0) {
        int nw = (blockDim.x + 31) >> 5;
        v = (lane < nw) ? wmax[lane] : 0.f;
#pragma unroll
        for (int o = 8; o > 0; o >>= 1)
            v = fmaxf(v, __shfl_xor_sync(0xffffffffu, v, o));
        if (lane == 0) atomicMax(&g_max_bits[slot], __float_as_int(v));
    }
}

// ---------------- prep: zero maxima, weight scales + packed int8 weights ----
__global__ void k_prep(const float* __restrict__ w1, const float* __restrict__ w2,
                       const float* __restrict__ fw1, const float* __restrict__ fw2)
{
    if (blockIdx.x == 0 && threadIdx.x < 4) g_max_bits[threadIdx.x] = 0;

    const float* src; int n;
    switch (blockIdx.x) {
        case 0:  src = w1;  n = 450;   break;
        case 1:  src = w2;  n = 2400;  break;
        case 2:  src = fw1; n = 48000; break;
        default: src = fw2; n = 1200;  break;
    }
    float m = 0.f;
    for (int i = threadIdx.x; i < n; i += blockDim.x)
        m = fmaxf(m, fabsf(src[i]));
#pragma unroll
    for (int o = 16; o > 0; o >>= 1)
        m = fmaxf(m, __shfl_xor_sync(0xffffffffu, m, o));
    __shared__ float smax[8];
    __shared__ float sscale;
    int lane = threadIdx.x & 31, w = threadIdx.x >> 5;
    if (lane == 0) smax[w] = m;
    __syncthreads();
    if (threadIdx.x == 0) {
        float mm = smax[0];
        for (int i = 1; i < (int)((blockDim.x + 31) >> 5); i++) mm = fmaxf(mm, smax[i]);
        float s = mm / 127.0f + 1e-12f;
        g_ws[blockIdx.x] = s;
        sscale = s;
    }
    __syncthreads();
    float s = sscale;

    if (blockIdx.x == 0) {
        // w1 [6,3,5,5] -> [co][tap] word of (c0,c1,c2,0)
        for (int t = threadIdx.x; t < 150; t += blockDim.x) {
            int co = t / 25, tap = t % 25;
            g_w1p[t] = (int)pack4(__float2int_rn(w1[co * 75 + tap] / s),
                                  __float2int_rn(w1[co * 75 + 25 + tap] / s),
                                  __float2int_rn(w1[co * 75 + 50 + tap] / s), 0);
        }
    } else if (blockIdx.x == 1) {
        // w2 [16,6,5,5] -> [co][tap][wi] words of 4 channels (6 real + 2 pad)
        for (int t = threadIdx.x; t < 800; t += blockDim.x) {
            int co = t / 50, rem = t % 50, tap = rem / 2, wi = rem % 2;
            int q[4];
#pragma unroll
            for (int b = 0; b < 4; b++) {
                int ci = wi * 4 + b;
                q[b] = (ci < 6) ? __float2int_rn(w2[co * 150 + ci * 25 + tap] / s) : 0;
            }
            g_w2p[t] = (int)pack4(q[0], q[1], q[2], q[3]);
        }
    } else if (blockIdx.x == 2) {
        // fw1 [120,400] -> k-major [k_word][col]; act idx i = pix*16+c maps to
        // ref k = c*25 + pix
        for (int t = threadIdx.x; t < 12000; t += blockDim.x) {
            int k = t / 120, col = t % 120;
            int q[4];
#pragma unroll
            for (int b = 0; b < 4; b++) {
                int i = 4 * k + b;
                int c = i & 15, pix = i >> 4;
                q[b] = __float2int_rn(fw1[col * 400 + c * 25 + pix] / s);
            }
            g_fw1p[t] = (int)pack4(q[0], q[1], q[2], q[3]);
        }
    } else {
        // fw2 [10,120] -> [col][k_word]
        for (int t = threadIdx.x; t < 300; t += blockDim.x) {
            int col = t / 30, j = t % 30;
            g_fw2p[t] = (int)pack4(__float2int_rn(fw2[col * 120 + 4 * j + 0] / s),
                                   __float2int_rn(fw2[col * 120 + 4 * j + 1] / s),
                                   __float2int_rn(fw2[col * 120 + 4 * j + 2] / s),
                                   __float2int_rn(fw2[col * 120 + 4 * j + 3] / s));
        }
    }
}

// ---------------- global abs-max of x ----------------
__global__ void k_xmax(const float* __restrict__ x, int n)
{
    float m = 0.f;
    int n4 = n >> 2;
    const float4* x4 = reinterpret_cast<const float4*>(x);
    for (int i = blockIdx.x * blockDim.x + threadIdx.x; i < n4; i += gridDim.x * blockDim.x) {
        float4 v = x4[i];
        m = fmaxf(m, fmaxf(fmaxf(fabsf(v.x), fabsf(v.y)), fmaxf(fabsf(v.z), fabsf(v.w))));
    }
    if (blockIdx.x == 0 && threadIdx.x == 0)
        for (int i = n4 << 2; i < n; i++) m = fmaxf(m, fabsf(x[i]));
    block_atomic_max(m, 0);
}

// ---------------- conv1 + bias + relu + maxpool (dp4a, half-width split) -----
// thread = (img, co, ph, half): 2 conv rows x 14 conv cols -> 7 pooled outputs.
// regs: acc 2x14 + xv 18 -> no spills.
__global__ void __launch_bounds__(512) k_conv1(const float* __restrict__ x,
                                               const float* __restrict__ b1,
                                               int nimg)
{
    __shared__ unsigned sx[3 * 1024];   // [img][32*32] packed NHWC4
    __shared__ int sw[150];
    const float s0 = __int_as_float(g_max_bits[0]) / 127.0f + 1e-12f;
    const float inv0 = 1.0f / s0;
    const int base = blockIdx.x * 3;
    const int count = min(3, nimg - base);

    for (int i = threadIdx.x; i < count * 1024; i += 512) {
        int img = i >> 10, p = i & 1023;
        const float* xp = x + (size_t)(base + img) * 3072 + p;
        sx[i] = pack4(q_s8m(xp[0], inv0), q_s8m(xp[1024], inv0),
                      q_s8m(xp[2048], inv0), 0);
    }
    for (int i = threadIdx.x; i < 150; i += 512) sw[i] = g_w1p[i];
    __syncthreads();

    float lmax = 0.f;
    int img_l = threadIdx.x / 168;
    int r = threadIdx.x % 168;
    if (img_l < count) {
        int co = r / 28, rem = r % 28, ph = rem >> 1, half = rem & 1;
        const unsigned* xim = sx + img_l * 1024 + (2 * ph) * 32 + half * 14;
        const int* wk = sw + co * 25;
        int acc0[14], acc1[14];
#pragma unroll
        for (int i = 0; i < 14; i++) { acc0[i] = 0; acc1[i] = 0; }
#pragma unroll
        for (int r6 = 0; r6 < 6; r6++) {
            unsigned xv[18];
#pragma unroll
            for (int j = 0; j < 18; j++) xv[j] = xim[r6 * 32 + j];
            if (r6 < 5) {
#pragma unroll
                for (int kw = 0; kw < 5; kw++) {
                    unsigned wv = (unsigned)wk[r6 * 5 + kw];
#pragma unroll
                    for (int ow = 0; ow < 14; ow++)
                        acc0[ow] = dp4a_ss(xv[ow + kw], wv, acc0[ow]);
                }
            }
            if (r6 >= 1) {
#pragma unroll
                for (int kw = 0; kw < 5; kw++) {
                    unsigned wv = (unsigned)wk[(r6 - 1) * 5 + kw];
#pragma unroll
                    for (int ow = 0; ow < 14; ow++)
                        acc1[ow] = dp4a_ss(xv[ow + kw], wv, acc1[ow]);
                }
            }
        }
        float sp = s0 * g_ws[0];
        int qb = __float2int_rn(b1[co] / sp);
        float* op = g_out1 + ((size_t)(base + img_l) * 196 + ph * 14 + half * 7) * 6 + co;
#pragma unroll
        for (int pw = 0; pw < 7; pw++) {
            int m = max(max(acc0[2 * pw], acc0[2 * pw + 1]),
                        max(acc1[2 * pw], acc1[2 * pw + 1]));
            float v = sp * (float)max(m + qb, 0);
            lmax = fmaxf(lmax, v);
            op[pw * 6] = v;
        }
    }
    block_atomic_max(lmax, 1);
}

// ---------------- conv2 + bias + relu + maxpool (dp4a, overlap split) --------
// thread = (img, co, ph, half): 6 conv cols starting at half*4 -> 3 pooled
// (middle pooled col computed by both halves with identical value).
__global__ void __launch_bounds__(512) k_conv2(const float* __restrict__ b2, int nimg)
{
    __shared__ unsigned sx[3 * 392];    // [img][14*14][2] packed NHWC8
    __shared__ int sw[800];
    const float s1 = __int_as_float(g_max_bits[1]) / 255.0f + 1e-12f;
    const float inv1 = 1.0f / s1;
    const int base = blockIdx.x * 3;
    const int count = min(3, nimg - base);

    for (int i = threadIdx.x; i < count * 196; i += 512) {
        int img = i / 196, p = i % 196;
        const float2* ap = (const float2*)(g_out1 + ((size_t)(base + img) * 196 + p) * 6);
        float2 v0 = ap[0], v1 = ap[1], v2 = ap[2];
        sx[i * 2]     = pack4(q_u8m(v0.x, inv1), q_u8m(v0.y, inv1),
                              q_u8m(v1.x, inv1), q_u8m(v1.y, inv1));
        sx[i * 2 + 1] = pack4(q_u8m(v2.x, inv1), q_u8m(v2.y, inv1), 0, 0);
    }
    for (int i = threadIdx.x; i < 800; i += 512) sw[i] = g_w2p[i];
    __syncthreads();

    float lmax = 0.f;
    int img_l = threadIdx.x / 160;
    int r = threadIdx.x % 160;
    if (img_l < count) {
        int co = r / 10, rem = r % 10, ph = rem >> 1, half = rem & 1;
        const unsigned* xim = sx + img_l * 392 + (2 * ph) * 28 + half * 8;
        const int* wk = sw + co * 50;
        int acc0[6], acc1[6];
#pragma unroll
        for (int i = 0; i < 6; i++) { acc0[i] = 0; acc1[i] = 0; }
#pragma unroll
        for (int r6 = 0; r6 < 6; r6++) {
            unsigned xv[20];
#pragma unroll
            for (int j = 0; j < 20; j++) xv[j] = xim[r6 * 28 + j];
            if (r6 < 5) {
#pragma unroll
                for (int kw = 0; kw < 5; kw++) {
                    unsigned w0 = (unsigned)wk[(r6 * 5 + kw) * 2];
                    unsigned w1 = (unsigned)wk[(r6 * 5 + kw) * 2 + 1];
#pragma unroll
                    for (int ow = 0; ow < 6; ow++)
                        acc0[ow] = dp4a_us(xv[(ow + kw) * 2 + 1], w1,
                                   dp4a_us(xv[(ow + kw) * 2], w0, acc0[ow]));
                }
            }
            if (r6 >= 1) {
#pragma unroll
                for (int kw = 0; kw < 5; kw++) {
                    unsigned w0 = (unsigned)wk[((r6 - 1) * 5 + kw) * 2];
                    unsigned w1 = (unsigned)wk[((r6 - 1) * 5 + kw) * 2 + 1];
#pragma unroll
                    for (int ow = 0; ow < 6; ow++)
                        acc1[ow] = dp4a_us(xv[(ow + kw) * 2 + 1], w1,
                                   dp4a_us(xv[(ow + kw) * 2], w0, acc1[ow]));
                }
            }
        }
        float sp = s1 * g_ws[1];
        int qb = __float2int_rn(b2[co] / sp);
        float* op = g_out2 + ((size_t)(base + img_l) * 25 + ph * 5 + half * 2) * 16 + co;
#pragma unroll
        for (int t = 0; t < 3; t++) {
            int m = max(max(acc0[2 * t], acc0[2 * t + 1]),
                        max(acc1[2 * t], acc1[2 * t + 1]));
            float v = sp * (float)max(m + qb, 0);
            lmax = fmaxf(lmax, v);
            op[t * 16] = v;
        }
    }
    block_atomic_max(lmax, 2);
}

// ---------------- fc1 + bias + relu (dp4a, smem weights) ----------------
// 32 rows/block; dyn smem: act [32][101] words + weights k-major [100][120].
// 240 compute threads: 8 row-groups (4 rows) x 30 col-groups (4 cols, int4 LDS).
__global__ void __launch_bounds__(256) k_fc1(const float* __restrict__ fb1, int nimg)
{
    extern __shared__ unsigned dyn[];
    unsigned* sa = dyn;                 // 32*101 = 3232 words
    int* sw = (int*)(dyn + 32 * 101);   // 12000 words (16B-aligned: 3232*4=12928)
    const float s2 = __int_as_float(g_max_bits[2]) / 255.0f + 1e-12f;
    const float inv2 = 1.0f / s2;
    const int row0 = blockIdx.x * 32;

    for (int i = threadIdx.x; i < 3000; i += 256)
        ((int4*)sw)[i] = ((const int4*)g_fw1p)[i];
    for (int i = threadIdx.x; i < 3200; i += 256) {
        int rr = i / 100, j = i % 100;
        unsigned wv = 0;
        if (row0 + rr < nimg) {
            float4 v = *(const float4*)(g_out2 + (size_t)(row0 + rr) * 400 + 4 * j);
            wv = pack4(q_u8m(v.x, inv2), q_u8m(v.y, inv2),
                       q_u8m(v.z, inv2), q_u8m(v.w, inv2));
        }
        sa[rr * 101 + j] = wv;
    }
    __syncthreads();

    float lmax = 0.f;
    if (threadIdx.x < 240) {
        int rg = threadIdx.x / 30, cg = threadIdx.x % 30;
        int acc[4][4];
#pragma unroll
        for (int i = 0; i < 4; i++)
#pragma unroll
            for (int j = 0; j < 4; j++) acc[i][j] = 0;

        const unsigned* ap = sa + (rg * 4) * 101;
#pragma unroll 4
        for (int k = 0; k < 100; k++) {
            unsigned a0 = ap[k], a1 = ap[101 + k], a2 = ap[202 + k], a3 = ap[303 + k];
            int4 w = *(const int4*)(sw + k * 120 + cg * 4);
            acc[0][0] = dp4a_us(a0, (unsigned)w.x, acc[0][0]);
            acc[0][1] = dp4a_us(a0, (unsigned)w.y, acc[0][1]);
            acc[0][2] = dp4a_us(a0, (unsigned)w.z, acc[0][2]);
            acc[0][3] = dp4a_us(a0, (unsigned)w.w, acc[0][3]);
            acc[1][0] = dp4a_us(a1, (unsigned)w.x, acc[1][0]);
            acc[1][1] = dp4a_us(a1, (unsigned)w.y, acc[1][1]);
            acc[1][2] = dp4a_us(a1, (unsigned)w.z, acc[1][2]);
            acc[1][3] = dp4a_us(a1, (unsigned)w.w, acc[1][3]);
            acc[2][0] = dp4a_us(a2, (unsigned)w.x, acc[2][0]);
            acc[2][1] = dp4a_us(a2, (unsigned)w.y, acc[2][1]);
            acc[2][2] = dp4a_us(a2, (unsigned)w.z, acc[2][2]);
            acc[2][3] = dp4a_us(a2, (unsigned)w.w, acc[2][3]);
            acc[3][0] = dp4a_us(a3, (unsigned)w.x, acc[3][0]);
            acc[3][1] = dp4a_us(a3, (unsigned)w.y, acc[3][1]);
            acc[3][2] = dp4a_us(a3, (unsigned)w.z, acc[3][2]);
            acc[3][3] = dp4a_us(a3, (unsigned)w.w, acc[3][3]);
        }
        float sp = s2 * g_ws[2];
#pragma unroll
        for (int j = 0; j < 4; j++) {
            int col = cg * 4 + j;
            int qb = __float2int_rn(__ldg(&fb1[col]) / sp);
#pragma unroll
            for (int i = 0; i < 4; i++) {
                int row = row0 + rg * 4 + i;
                float v = sp * (float)max(acc[i][j] + qb, 0);
                lmax = fmaxf(lmax, v);
                if (row < nimg) g_out3[(size_t)row * 120 + col] = v;
            }
        }
    }
    block_atomic_max(lmax, 3);
}

// ---------------- fc2 + bias (dp4a, final output) ----------------
__global__ void __launch_bounds__(64) k_fc2(const float* __restrict__ fb2,
                                            float* __restrict__ out, int nimg)
{
    __shared__ unsigned sa[64 * 31];
    __shared__ int sw[300];
    const float s3 = __int_as_float(g_max_bits[3]) / 255.0f + 1e-12f;
    const float inv3 = 1.0f / s3;
    const int row0 = blockIdx.x * 64;

    for (int i = threadIdx.x; i < 300; i += 64) sw[i] = g_fw2p[i];
    for (int i = threadIdx.x; i < 64 * 30; i += 64) {
        int rr = i / 30, j = i % 30;
        unsigned wv = 0;
        if (row0 + rr < nimg) {
            float4 v = *(const float4*)(g_out3 + (size_t)(row0 + rr) * 120 + 4 * j);
            wv = pack4(q_u8m(v.x, inv3), q_u8m(v.y, inv3),
                       q_u8m(v.z, inv3), q_u8m(v.w, inv3));
        }
        sa[rr * 31 + j] = wv;
    }
    __syncthreads();

    int row = row0 + threadIdx.x;
    int acc[10];
#pragma unroll
    for (int c = 0; c < 10; c++) acc[c] = 0;
    const unsigned* ar = sa + threadIdx.x * 31;
#pragma unroll 5
    for (int k = 0; k < 30; k++) {
        unsigned a = ar[k];
#pragma unroll
        for (int c = 0; c < 10; c++)
            acc[c] = dp4a_us(a, (unsigned)sw[c * 30 + k], acc[c]);
    }
    float sp = s3 * g_ws[3];
    if (row < nimg) {
#pragma unroll
        for (int c = 0; c < 10; c++) {
            int qb = __float2int_rn(__ldg(&fb2[c]) / sp);
            out[(size_t)row * 10 + c] = sp * (float)(acc[c] + qb);
        }
    }
}

// ---------------- launch ----------------
extern "C" void kernel_launch(void* const* d_in, const int* in_sizes, int n_in,
                              void* d_out, int out_size)
{
    const float* x   = (const float*)d_in[0];
    const float* w1  = (const float*)d_in[1];
    const float* b1  = (const float*)d_in[2];
    const float* w2  = (const float*)d_in[3];
    const float* b2  = (const float*)d_in[4];
    const float* fw1 = (const float*)d_in[5];
    const float* fb1 = (const float*)d_in[6];
    const float* fw2 = (const float*)d_in[7];
    const float* fb2 = (const float*)d_in[8];
    float* out = (float*)d_out;
    const int nimg = in_sizes[0] / (3 * 32 * 32);

    const int fc1_dyn = (32 * 101 + 12000) * (int)sizeof(int);
    cudaFuncSetAttribute(k_fc1, cudaFuncAttributeMaxDynamicSharedMemorySize, fc1_dyn);

    k_prep<<<4, 256>>>(w1, w2, fw1, fw2);
    k_xmax<<<2048, 256>>>(x, in_sizes[0]);
    k_conv1<<<(nimg + 2) / 3, 512>>>(x, b1, nimg);
    k_conv2<<<(nimg + 2) / 3, 512>>>(b2, nimg);
    k_fc1<<<(nimg + 31) / 32, 256, fc1_dyn>>>(fb1, nimg);
    k_fc2<<<(nimg + 63) / 64, 64>>>(fb2, out, nimg);
}